// round 2
// baseline (speedup 1.0000x reference)
#include <cuda_runtime.h>
#include <cuda_bf16.h>
#include <math.h>

#define TN     256
#define DDIM   6
#define NEXP   540
#define NGEO   20
#define KPHI   27
#define NPROB  560          // 540 experts + 20 baselines
#define NTEST  1024
#define PACK   32896        // 256*257/2
#define JIT    1e-4f

// ---------------- static device scratch ----------------
__device__ float g_L[(size_t)NPROB * PACK];      // packed column-major lower L
__device__ float g_alpha[NPROB * TN];
__device__ float g_invd[NPROB * TN];
__device__ int   g_route_e[NTEST];
__device__ int   g_route_g[NTEST];
__device__ int   g_used[NPROB];
__device__ float g_mu_e[NTEST],  g_var_e[NTEST],  g_prior_e[NTEST];
__device__ float g_mu_b[NTEST],  g_var_b[NTEST],  g_prior_b[NTEST];

__device__ __forceinline__ int cpidx(int j) { return j * TN - ((j * (j - 1)) >> 1); }

// ---------------- kernel 0: clear used flags ----------------
__global__ void k_zero() {
    int i = blockIdx.x * blockDim.x + threadIdx.x;
    if (i < NPROB) g_used[i] = 0;
}

// ---------------- kernel 1: 2-level GMM routing ----------------
__global__ void k_route(const float* __restrict__ Xt,
                        const float* __restrict__ smean, const float* __restrict__ sscale,
                        const float* __restrict__ gm,    const float* __restrict__ glv,
                        const float* __restrict__ glw,
                        const float* __restrict__ pm,    const float* __restrict__ plv,
                        const float* __restrict__ plw,
                        const int*   __restrict__ nmask)
{
    int n = blockIdx.x * blockDim.x + threadIdx.x;
    if (n >= NTEST) return;
    float xs[DDIM];
#pragma unroll
    for (int d = 0; d < DDIM; ++d) xs[d] = (Xt[n * DDIM + d] - smean[d]) / sscale[d];

    float best = -3e38f; int gb = 0;
    for (int gi = 0; gi < NGEO; ++gi) {
        float acc = 0.f;
#pragma unroll
        for (int d = 0; d < DDIM; ++d) {
            float lv = glv[gi * DDIM + d];
            float t  = xs[d] - gm[gi * DDIM + d];
            acc += lv + t * t * expf(-lv);
        }
        float lp = glw[gi] - 0.5f * acc;       // D*log(2pi) constant dropped
        if (lp > best) { best = lp; gb = gi; }
    }
    float bestp = -3e38f; int kb = 0;
    for (int kk = 0; kk < KPHI; ++kk) {
        int base = (gb * KPHI + kk) * DDIM;
        float acc = 0.f;
#pragma unroll
        for (int d = 0; d < DDIM; ++d) {
            float lv = plv[base + d];
            float t  = xs[d] - pm[base + d];
            acc += lv + t * t * expf(-lv);
        }
        float lp = plw[gb * KPHI + kk] - 0.5f * acc;
        if (lp > bestp) { bestp = lp; kb = kk; }
    }
    int e = gb * KPHI + kb;
    g_route_e[n] = e;
    g_route_g[n] = gb;
    if (nmask[e] != 0) g_used[e] = 1;          // null experts never factorized
    g_used[NEXP + gb] = 1;
}

// ---------------- kernel 2: build K, blocked Cholesky, alpha solve, export ----------------
// smem layout (floats): sA[PACK] | sXp[TN*8] | sPan[TN*8] | sVec[TN] | sId[TN]
#define SMEM_FLOATS (PACK + TN*8 + TN*8 + TN + TN)

__global__ void __launch_bounds__(TN, 1) k_factor(
    const float* __restrict__ X_exp,  const float* __restrict__ Y_exp,
    const float* __restrict__ X_base, const float* __restrict__ Y_base,
    const float* __restrict__ lls_e, const float* __restrict__ los_e, const float* __restrict__ lno_e,
    const float* __restrict__ lls_b, const float* __restrict__ los_b, const float* __restrict__ lno_b)
{
    int b = blockIdx.x;
    if (!g_used[b]) return;

    extern __shared__ float sm[];
    float* sA   = sm;
    float* sXp  = sA + PACK;       // padded X: [256][8]
    float* sPan = sXp + TN * 8;    // panel rows transposed: [row][8]
    float* sVec = sPan + TN * 8;
    float* sId  = sVec + TN;

    int tid = threadIdx.x;

    const float* Xs; const float* Ys; float lls, los, lno;
    if (b < NEXP) {
        Xs = X_exp + (size_t)b * TN * DDIM;  Ys = Y_exp + b * TN;
        lls = lls_e[b]; los = los_e[b]; lno = lno_e[b];
    } else {
        int gb = b - NEXP;
        Xs = X_base + (size_t)gb * TN * DDIM; Ys = Y_base + gb * TN;
        lls = lls_b[gb]; los = los_b[gb]; lno = lno_b[gb];
    }
    float ls2 = expf(2.f * lls);
    float osv = expf(los);
    float nv  = expf(lno) + JIT;
    float c0  = -0.5f / ls2;

    // load X padded to 8 floats/row (pad = 0)
    {
        int i = tid;            // one row per thread
        float v[8];
#pragma unroll
        for (int d = 0; d < DDIM; ++d) v[d] = Xs[i * DDIM + d];
        v[6] = 0.f; v[7] = 0.f;
        float4* dst = (float4*)&sXp[i * 8];
        dst[0] = make_float4(v[0], v[1], v[2], v[3]);
        dst[1] = make_float4(v[4], v[5], v[6], v[7]);
    }
    __syncthreads();

    // ---- build K (packed column-major lower) ----
    {
        const float4* X4 = (const float4*)sXp;
        int off = 0;
        for (int j = 0; j < TN; ++j) {
            int i = j + tid;
            if (i < TN) {
                float4 xi0 = X4[i * 2], xi1 = X4[i * 2 + 1];
                float4 xj0 = X4[j * 2], xj1 = X4[j * 2 + 1];
                float t0 = xi0.x - xj0.x, t1 = xi0.y - xj0.y, t2 = xi0.z - xj0.z, t3 = xi0.w - xj0.w;
                float t4 = xi1.x - xj1.x, t5 = xi1.y - xj1.y;
                float d2 = t0*t0 + t1*t1 + t2*t2 + t3*t3 + t4*t4 + t5*t5;
                float k = osv * __expf(c0 * d2);
                if (tid == 0) k = osv + nv;     // exact diagonal
                sA[off + tid] = k;
            }
            off += TN - j;
        }
    }
    __syncthreads();

    // ---- blocked Cholesky, panel width 8 ----
    for (int q = 0; q < 32; ++q) {
        int j0 = q * 8;
        // redundant 8x8 diag Cholesky in registers (all threads)
        float Ld[8][8];
        float dinv[8];
#pragma unroll
        for (int c = 0; c < 8; ++c) {
            int base = cpidx(j0 + c);
#pragma unroll
            for (int r = 0; r < 8; ++r)
                if (r >= c) Ld[r][c] = sA[base + (r - c)];
        }
#pragma unroll
        for (int c = 0; c < 8; ++c) {
            float dsq = Ld[c][c];
#pragma unroll
            for (int p = 0; p < 8; ++p) if (p < c) dsq -= Ld[c][p] * Ld[c][p];
            float dl = sqrtf(dsq);
            Ld[c][c] = dl;
            float inv = 1.0f / dl;
            dinv[c] = inv;
#pragma unroll
            for (int r = 0; r < 8; ++r) {
                if (r > c) {
                    float v = Ld[r][c];
#pragma unroll
                    for (int p = 0; p < 8; ++p) if (p < c) v -= Ld[r][p] * Ld[c][p];
                    Ld[r][c] = v * inv;
                }
            }
        }

        int R = TN - j0 - 8;
        // panel solve: rows below diag block, one per thread
        if (tid < R) {
            int i = j0 + 8 + tid;
            float a[8];
#pragma unroll
            for (int c = 0; c < 8; ++c) a[c] = sA[cpidx(j0 + c) + (i - (j0 + c))];
#pragma unroll
            for (int c = 0; c < 8; ++c) {
                float v = a[c];
#pragma unroll
                for (int p = 0; p < 8; ++p) if (p < c) v -= a[p] * Ld[c][p];
                a[c] = v * dinv[c];
            }
#pragma unroll
            for (int c = 0; c < 8; ++c) sA[cpidx(j0 + c) + (i - (j0 + c))] = a[c];
            float4* sp = (float4*)&sPan[tid * 8];
            sp[0] = make_float4(a[0], a[1], a[2], a[3]);
            sp[1] = make_float4(a[4], a[5], a[6], a[7]);
        }
        // write diag block rows (static indexing to keep Ld in registers)
#pragma unroll
        for (int r = 0; r < 8; ++r) {
            if (tid == r) {
#pragma unroll
                for (int c = 0; c < 8; ++c)
                    if (c <= r) sA[cpidx(j0 + c) + (r - c)] = Ld[r][c];
            }
        }
        __syncthreads();

        // trailing SYRK update
        if (q < 31 && tid < R) {
            int i = j0 + 8 + tid;
            float4 p0 = ((float4*)&sPan[tid * 8])[0];
            float4 p1 = ((float4*)&sPan[tid * 8])[1];
            int idx = cpidx(j0 + 8) + (i - (j0 + 8));
#pragma unroll 4
            for (int k = j0 + 8; k <= i; ++k) {
                int kk = k - (j0 + 8);
                float4 q0 = ((float4*)&sPan[kk * 8])[0];
                float4 q1 = ((float4*)&sPan[kk * 8])[1];
                float v = sA[idx];
                v -= p0.x*q0.x + p0.y*q0.y + p0.z*q0.z + p0.w*q0.w
                   + p1.x*q1.x + p1.y*q1.y + p1.z*q1.z + p1.w*q1.w;
                sA[idx] = v;
                idx += 255 - k;
            }
        }
        __syncthreads();
    }

    // ---- inverse diagonal + export it ----
    {
        int j = tid;
        float inv = 1.0f / sA[cpidx(j)];
        sId[j] = inv;
        g_invd[b * TN + j] = inv;
        sVec[j] = Ys[j];
    }
    // ---- export L (coalesced) ----
    for (int idx = tid; idx < PACK; idx += TN)
        g_L[(size_t)b * PACK + idx] = sA[idx];
    __syncthreads();

    // ---- alpha = K^-1 y : forward then backward block-wide solves ----
    {
        int off = 0;
        for (int j = 0; j < TN; ++j) {
            float zj = sVec[j] * sId[j];
            if (tid == 0) sPan[j] = zj;          // z storage (sPan free now)
            int i = j + 1 + tid;
            if (i < TN) sVec[i] -= sA[off + (i - j)] * zj;
            off += TN - j;
            __syncthreads();
        }
    }
    {
        int ctid = cpidx(tid);
        for (int j = TN - 1; j >= 0; --j) {
            float aj = sPan[j] * sId[j];
            if (tid == 0) g_alpha[b * TN + j] = aj;
            if (tid < j) sPan[tid] -= sA[ctid + (j - tid)] * aj;
            __syncthreads();
        }
    }
}

// ---------------- kernel 3: per-point GP prediction (1 warp per point x {expert,baseline}) ----------------
__global__ void __launch_bounds__(256) k_predict(
    const float* __restrict__ Xt,
    const float* __restrict__ X_exp, const float* __restrict__ X_base,
    const float* __restrict__ lls_e, const float* __restrict__ los_e, const float* __restrict__ lno_e,
    const float* __restrict__ lls_b, const float* __restrict__ los_b, const float* __restrict__ lno_b,
    const int*   __restrict__ nmask)
{
    __shared__ float sZ[8][TN];
    int warp = threadIdx.x >> 5, lane = threadIdx.x & 31;
    int gw = blockIdx.x * 8 + warp;               // 0..2047
    if (gw >= 2 * NTEST) return;
    int n = gw >> 1;
    bool is_base = (gw & 1);

    int p; const float* Xtr; float lls, los, lno;
    if (!is_base) {
        int e = g_route_e[n];
        if (nmask[e] == 0) {
            if (lane == 0) { g_mu_e[n] = 0.f; g_var_e[n] = 1.f; g_prior_e[n] = 1.f; }
            return;
        }
        p = e; Xtr = X_exp + (size_t)e * TN * DDIM;
        lls = lls_e[e]; los = los_e[e]; lno = lno_e[e];
    } else {
        int g = g_route_g[n];
        p = NEXP + g; Xtr = X_base + (size_t)g * TN * DDIM;
        lls = lls_b[g]; los = los_b[g]; lno = lno_b[g];
    }
    float ls2 = expf(2.f * lls);
    float osv = expf(los);
    float nv  = expf(lno) + JIT;
    float c0  = -0.5f / ls2;

    float xt[DDIM];
#pragma unroll
    for (int d = 0; d < DDIM; ++d) xt[d] = Xt[n * DDIM + d];

    // kstar, 8 rows per lane
    float ks[8];
#pragma unroll
    for (int t = 0; t < 8; ++t) {
        int r = 32 * t + lane;
        float d2 = 0.f;
#pragma unroll
        for (int d = 0; d < DDIM; ++d) {
            float tv = xt[d] - Xtr[r * DDIM + d];
            d2 += tv * tv;
        }
        ks[t] = osv * __expf(c0 * d2);
    }

    const float* Lp  = g_L + (size_t)p * PACK;
    const float* alp = g_alpha + p * TN;
    const float* inv = g_invd  + p * TN;
    float* z = sZ[warp];

    float qq = 0.f;
#pragma unroll 1
    for (int T = 0; T < 8; ++T) {
        int r = 32 * T + lane;
        float acc = ks[T];
        // GEMV against previous tiles' solution
        int idx = r;                       // cp(0) + r
        int lim = 32 * T;
#pragma unroll 4
        for (int c = 0; c < lim; ++c) {
            acc -= Lp[idx] * z[c];
            idx += 255 - c;
        }
        // diagonal 32x32 triangular solve via shuffles
        float invv = inv[32 * T + lane];
        int c = 32 * T;
        int idd = cpidx(c) + (r - c);
#pragma unroll
        for (int s = 0; s < 32; ++s) {
            float zc = __shfl_sync(0xffffffffu, acc, s) * __shfl_sync(0xffffffffu, invv, s);
            if (lane == s) { z[c] = zc; qq += zc * zc; }
            if (lane > s) acc -= Lp[idd] * zc;
            idd += 255 - c;
            ++c;
        }
        __syncwarp();
    }

    float mu = 0.f;
#pragma unroll
    for (int t = 0; t < 8; ++t) mu += ks[t] * alp[32 * t + lane];
#pragma unroll
    for (int o = 16; o; o >>= 1) {
        mu += __shfl_xor_sync(0xffffffffu, mu, o);
        qq += __shfl_xor_sync(0xffffffffu, qq, o);
    }
    if (lane == 0) {
        float var = fmaxf(osv - qq, JIT) + nv;
        float prior = osv + nv;
        if (!is_base) { g_mu_e[n] = mu; g_var_e[n] = var; g_prior_e[n] = prior; }
        else          { g_mu_b[n] = mu; g_var_b[n] = var; g_prior_b[n] = prior; }
    }
}

// ---------------- kernel 4: rBCM combine ----------------
__global__ void k_combine(const int* __restrict__ nmask, float* __restrict__ out)
{
    int n = blockIdx.x * blockDim.x + threadIdx.x;
    if (n >= NTEST) return;
    int e = g_route_e[n];
    bool isnull = (nmask[e] == 0);
    float mue = g_mu_e[n], vare = g_var_e[n], pre = g_prior_e[n];
    float mub = g_mu_b[n], varb = g_var_b[n], prb = g_prior_b[n];
    float be = isnull ? 0.f : fmaxf(0.5f * (logf(pre) - logf(vare)), 0.f);
    float bb = fmaxf(0.5f * (logf(prb) - logf(varb)), 0.f);
    float prec = be / vare + bb / varb + (1.f - be - bb) / prb;
    prec = fmaxf(prec, 1e-6f);
    float mean = (be * mue / vare + bb * mub / varb) / prec;
    out[n] = mean;
    out[NTEST + n] = 1.f / prec;
}

// ---------------- launch ----------------
extern "C" void kernel_launch(void* const* d_in, const int* in_sizes, int n_in,
                              void* d_out, int out_size)
{
    const float* X_test   = (const float*)d_in[0];
    const float* X_exp    = (const float*)d_in[1];
    const float* Y_exp    = (const float*)d_in[2];
    const float* X_base   = (const float*)d_in[3];
    const float* Y_base   = (const float*)d_in[4];
    const float* lls_e    = (const float*)d_in[5];
    const float* los_e    = (const float*)d_in[6];
    const float* lno_e    = (const float*)d_in[7];
    const float* lls_b    = (const float*)d_in[8];
    const float* los_b    = (const float*)d_in[9];
    const float* lno_b    = (const float*)d_in[10];
    const float* smean    = (const float*)d_in[11];
    const float* sscale   = (const float*)d_in[12];
    const float* gm       = (const float*)d_in[13];
    const float* glv      = (const float*)d_in[14];
    const float* glw      = (const float*)d_in[15];
    const float* pm       = (const float*)d_in[16];
    const float* plv      = (const float*)d_in[17];
    const float* plw      = (const float*)d_in[18];
    const int*   nmask    = (const int*)d_in[19];
    float* out = (float*)d_out;

    static_assert(SMEM_FLOATS * 4 <= 232448, "smem");
    cudaFuncSetAttribute(k_factor, cudaFuncAttributeMaxDynamicSharedMemorySize,
                         SMEM_FLOATS * 4);

    k_zero<<<(NPROB + 255) / 256, 256>>>();
    k_route<<<(NTEST + 255) / 256, 256>>>(X_test, smean, sscale, gm, glv, glw,
                                          pm, plv, plw, nmask);
    k_factor<<<NPROB, TN, SMEM_FLOATS * 4>>>(X_exp, Y_exp, X_base, Y_base,
                                             lls_e, los_e, lno_e,
                                             lls_b, los_b, lno_b);
    k_predict<<<(2 * NTEST + 7) / 8, 256>>>(X_test, X_exp, X_base,
                                            lls_e, los_e, lno_e,
                                            lls_b, los_b, lno_b, nmask);
    k_combine<<<(NTEST + 255) / 256, 256>>>(nmask, out);
}

// round 3
// speedup vs baseline: 1.4239x; 1.4239x over previous
#include <cuda_runtime.h>
#include <cuda_bf16.h>
#include <math.h>

#define TN     256
#define DDIM   6
#define NEXP   540
#define NGEO   20
#define KPHI   27
#define NPROB  560          // 540 experts + 20 baselines
#define NTEST  1024
#define PACK   32896        // 256*257/2
#define JIT    1e-4f

// ---------------- static device scratch ----------------
__device__ float g_L[(size_t)NPROB * PACK];      // packed column-major lower L
__device__ float g_w[NPROB * TN];                // w = L^-1 y
__device__ float g_invd[NPROB * TN];
__device__ int   g_route_e[NTEST];
__device__ int   g_route_g[NTEST];
__device__ int   g_used[NPROB];
__device__ float g_mu_e[NTEST],  g_var_e[NTEST],  g_prior_e[NTEST];
__device__ float g_mu_b[NTEST],  g_var_b[NTEST],  g_prior_b[NTEST];

__device__ __forceinline__ int cpidx(int j) { return j * TN - ((j * (j - 1)) >> 1); }

// ---------------- kernel 0 ----------------
__global__ void k_zero() {
    int i = blockIdx.x * blockDim.x + threadIdx.x;
    if (i < NPROB) g_used[i] = 0;
}

// ---------------- kernel 1: 2-level GMM routing ----------------
__global__ void k_route(const float* __restrict__ Xt,
                        const float* __restrict__ smean, const float* __restrict__ sscale,
                        const float* __restrict__ gm,    const float* __restrict__ glv,
                        const float* __restrict__ glw,
                        const float* __restrict__ pm,    const float* __restrict__ plv,
                        const float* __restrict__ plw,
                        const int*   __restrict__ nmask)
{
    int n = blockIdx.x * blockDim.x + threadIdx.x;
    if (n >= NTEST) return;
    float xs[DDIM];
#pragma unroll
    for (int d = 0; d < DDIM; ++d) xs[d] = (Xt[n * DDIM + d] - smean[d]) / sscale[d];

    float best = -3e38f; int gb = 0;
    for (int gi = 0; gi < NGEO; ++gi) {
        float acc = 0.f;
#pragma unroll
        for (int d = 0; d < DDIM; ++d) {
            float lv = glv[gi * DDIM + d];
            float t  = xs[d] - gm[gi * DDIM + d];
            acc += lv + t * t * expf(-lv);
        }
        float lp = glw[gi] - 0.5f * acc;
        if (lp > best) { best = lp; gb = gi; }
    }
    float bestp = -3e38f; int kb = 0;
    for (int kk = 0; kk < KPHI; ++kk) {
        int base = (gb * KPHI + kk) * DDIM;
        float acc = 0.f;
#pragma unroll
        for (int d = 0; d < DDIM; ++d) {
            float lv = plv[base + d];
            float t  = xs[d] - pm[base + d];
            acc += lv + t * t * expf(-lv);
        }
        float lp = plw[gb * KPHI + kk] - 0.5f * acc;
        if (lp > bestp) { bestp = lp; kb = kk; }
    }
    int e = gb * KPHI + kb;
    g_route_e[n] = e;
    g_route_g[n] = gb;
    if (nmask[e] != 0) g_used[e] = 1;
    g_used[NEXP + gb] = 1;
}

// ---------------- kernel 2: build K, blocked Cholesky, w-solve, export ----------------
// smem (floats): sA[PACK] | sXp[256*8] | sPan[256*8] | sW[256]
#define SMEM_FLOATS (PACK + TN*8 + TN*8 + TN)

__global__ void __launch_bounds__(512, 1) k_factor(
    const float* __restrict__ X_exp,  const float* __restrict__ Y_exp,
    const float* __restrict__ X_base, const float* __restrict__ Y_base,
    const float* __restrict__ lls_e, const float* __restrict__ los_e, const float* __restrict__ lno_e,
    const float* __restrict__ lls_b, const float* __restrict__ los_b, const float* __restrict__ lno_b)
{
    int b = blockIdx.x;
    if (!g_used[b]) return;

    extern __shared__ float sm[];
    float* sA   = sm;
    float* sXp  = sA + PACK;       // X padded [256][8]; later reused for inv-diag
    float* sPan = sXp + TN * 8;    // panel rows [256][8]
    float* sW   = sPan + TN * 8;   // y -> w

    int tid  = threadIdx.x;
    int wid  = tid >> 5;
    int lane = tid & 31;

    const float* Xs; const float* Ys; float lls, los, lno;
    if (b < NEXP) {
        Xs = X_exp + (size_t)b * TN * DDIM;  Ys = Y_exp + b * TN;
        lls = lls_e[b]; los = los_e[b]; lno = lno_e[b];
    } else {
        int gb = b - NEXP;
        Xs = X_base + (size_t)gb * TN * DDIM; Ys = Y_base + gb * TN;
        lls = lls_b[gb]; los = los_b[gb]; lno = lno_b[gb];
    }
    float ls2 = expf(2.f * lls);
    float osv = expf(los);
    float nv  = expf(lno) + JIT;
    float c0  = -0.5f / ls2;

    // load X padded + y
    if (tid < TN) {
        int i = tid;
        float v[8];
#pragma unroll
        for (int d = 0; d < DDIM; ++d) v[d] = Xs[i * DDIM + d];
        v[6] = 0.f; v[7] = 0.f;
        float4* dst = (float4*)&sXp[i * 8];
        dst[0] = make_float4(v[0], v[1], v[2], v[3]);
        dst[1] = make_float4(v[4], v[5], v[6], v[7]);
        sW[i] = Ys[i];
    }
    __syncthreads();

    // ---- build K: thread owns a fixed row, two threads split each row's column range
    {
        int row  = tid & 255;
        int half = tid >> 8;
        const float4* X4 = (const float4*)sXp;
        float4 xi0 = X4[row * 2], xi1 = X4[row * 2 + 1];
        int jmid = (row + 1) >> 1;
        int jlo = half ? jmid : 0;
        int jhi = half ? (row + 1) : jmid;
        int idx = cpidx(jlo) + row - jlo;
        for (int j = jlo; j < jhi; ++j) {
            float4 xj0 = X4[j * 2], xj1 = X4[j * 2 + 1];
            float t0 = xi0.x - xj0.x, t1 = xi0.y - xj0.y, t2 = xi0.z - xj0.z, t3 = xi0.w - xj0.w;
            float t4 = xi1.x - xj1.x, t5 = xi1.y - xj1.y;
            float d2 = t0*t0 + t1*t1 + t2*t2 + t3*t3 + t4*t4 + t5*t5;
            float kv = (j == row) ? (osv + nv) : (osv * __expf(c0 * d2));
            sA[idx] = kv;
            idx += 255 - j;
        }
    }
    __syncthreads();

    const float4* pan4 = (const float4*)sPan;

    // ---- blocked Cholesky, panel width 8 ----
    for (int q = 0; q < 32; ++q) {
        int j0   = q * 8;
        int base = j0 + 8;
        int R    = TN - base;            // rows below the diag block

        if (tid < TN) {
            // redundant 8x8 diag Cholesky in registers
            float Ld[8][8];
            float dinv[8];
#pragma unroll
            for (int c = 0; c < 8; ++c) {
                int bidx = cpidx(j0 + c);
#pragma unroll
                for (int r = 0; r < 8; ++r)
                    if (r >= c) Ld[r][c] = sA[bidx + (r - c)];
            }
#pragma unroll
            for (int c = 0; c < 8; ++c) {
                float dsq = Ld[c][c];
#pragma unroll
                for (int p = 0; p < 8; ++p) if (p < c) dsq -= Ld[c][p] * Ld[c][p];
                float dl = sqrtf(dsq);
                Ld[c][c] = dl;
                float inv = 1.0f / dl;
                dinv[c] = inv;
#pragma unroll
                for (int r = 0; r < 8; ++r) {
                    if (r > c) {
                        float v = Ld[r][c];
#pragma unroll
                        for (int p = 0; p < 8; ++p) if (p < c) v -= Ld[r][p] * Ld[c][p];
                        Ld[r][c] = v * inv;
                    }
                }
            }
            // panel solve: one row per thread
            if (tid < R) {
                int i = base + tid;
                float a[8];
#pragma unroll
                for (int c = 0; c < 8; ++c) a[c] = sA[cpidx(j0 + c) + (i - (j0 + c))];
#pragma unroll
                for (int c = 0; c < 8; ++c) {
                    float v = a[c];
#pragma unroll
                    for (int p = 0; p < 8; ++p) if (p < c) v -= a[p] * Ld[c][p];
                    a[c] = v * dinv[c];
                }
#pragma unroll
                for (int c = 0; c < 8; ++c) sA[cpidx(j0 + c) + (i - (j0 + c))] = a[c];
                float4* sp = (float4*)&sPan[tid * 8];
                sp[0] = make_float4(a[0], a[1], a[2], a[3]);
                sp[1] = make_float4(a[4], a[5], a[6], a[7]);
            }
            // write diag block back (static reg indexing)
#pragma unroll
            for (int r = 0; r < 8; ++r) {
                if (tid == r) {
#pragma unroll
                    for (int c = 0; c < 8; ++c)
                        if (c <= r) sA[cpidx(j0 + c) + (r - c)] = Ld[r][c];
                }
            }
        }
        __syncthreads();

        // ---- SYRK: warp per 8-row tile, 8 panel rows in registers, lanes span k ----
        if (R > 0) {
            int nt = (R + 7) >> 3;
            for (int rt = wid; rt < nt; rt += 16) {
                int r0 = rt << 3;
                float4 pi0[8], pi1[8];
#pragma unroll
                for (int rr = 0; rr < 8; ++rr) {
                    if (r0 + rr < R) {
                        pi0[rr] = pan4[(r0 + rr) * 2];
                        pi1[rr] = pan4[(r0 + rr) * 2 + 1];
                    } else {
                        pi0[rr] = make_float4(0.f, 0.f, 0.f, 0.f);
                        pi1[rr] = make_float4(0.f, 0.f, 0.f, 0.f);
                    }
                }
                int rmax = min(r0 + 7, R - 1);
                for (int kb = 0; kb <= rmax; kb += 32) {
                    int kk = kb + lane;
                    float4 q0 = make_float4(0.f, 0.f, 0.f, 0.f);
                    float4 q1 = q0;
                    if (kk <= rmax) {
                        q0 = pan4[kk * 2];
                        q1 = pan4[kk * 2 + 1];
                    }
                    int c = base + kk;
                    int cbase = c * TN - ((c * (c - 1)) >> 1);
#pragma unroll
                    for (int rr = 0; rr < 8; ++rr) {
                        int rho = r0 + rr;
                        if (kk <= rho && rho < R) {
                            int idx = cbase + (rho - kk);
                            float v = sA[idx];
                            v -= pi0[rr].x*q0.x + pi0[rr].y*q0.y + pi0[rr].z*q0.z + pi0[rr].w*q0.w
                               + pi1[rr].x*q1.x + pi1[rr].y*q1.y + pi1[rr].z*q1.z + pi1[rr].w*q1.w;
                            sA[idx] = v;
                        }
                    }
                }
            }
        }
        __syncthreads();
    }

    // ---- inverse diagonal (into sXp, reused) + export ----
    if (tid < TN) {
        float iv = 1.0f / sA[cpidx(tid)];
        sXp[tid] = iv;
        g_invd[b * TN + tid] = iv;
    }
    __syncthreads();

    if (wid == 0) {
        // warp 0: forward solve w = L^-1 y via warp-tiled substitution (smem L)
#pragma unroll 1
        for (int T = 0; T < 8; ++T) {
            int r = 32 * T + lane;
            float acc = sW[r];
            int lim = 32 * T;
            float a0 = 0.f, a1 = 0.f, a2 = 0.f, a3 = 0.f;
            int idx = r;
            for (int c = 0; c < lim; c += 4) {
                float z0 = sW[c], z1 = sW[c+1], z2 = sW[c+2], z3 = sW[c+3];
                float l0 = sA[idx]; idx += 255 - c;
                float l1 = sA[idx]; idx += 254 - c;
                float l2 = sA[idx]; idx += 253 - c;
                float l3 = sA[idx]; idx += 252 - c;
                a0 += l0 * z0; a1 += l1 * z1; a2 += l2 * z2; a3 += l3 * z3;
            }
            acc -= (a0 + a1) + (a2 + a3);
            float invv = sXp[r];
            int cb = 32 * T;
            // prefetch diag-block column values (address-independent of z)
            float dcol[32];
#pragma unroll
            for (int s = 0; s < 32; ++s)
                dcol[s] = sA[cpidx(cb + s) + (lane - s)];
            float myz = 0.f;
#pragma unroll
            for (int s = 0; s < 32; ++s) {
                float zc = __shfl_sync(0xffffffffu, acc, s) * __shfl_sync(0xffffffffu, invv, s);
                if (lane == s) myz = zc;
                if (lane > s) acc -= dcol[s] * zc;
            }
            sW[r] = myz;
            g_w[b * TN + r] = myz;
            __syncwarp();
        }
    } else {
        // warps 1..15: export L concurrently (float4, coalesced)
        const float4* s4 = (const float4*)sA;
        float4* d4 = (float4*)(g_L + (size_t)b * PACK);
        for (int i = tid - 32; i < PACK / 4; i += 480) d4[i] = s4[i];
    }
}

// ---------------- kernel 3: per-point prediction (1 warp per (point, model)) ----------------
__global__ void __launch_bounds__(256) k_predict(
    const float* __restrict__ Xt,
    const float* __restrict__ X_exp, const float* __restrict__ X_base,
    const float* __restrict__ lls_e, const float* __restrict__ los_e, const float* __restrict__ lno_e,
    const float* __restrict__ lls_b, const float* __restrict__ los_b, const float* __restrict__ lno_b,
    const int*   __restrict__ nmask)
{
    __shared__ float sZ[8][TN];
    int warp = threadIdx.x >> 5, lane = threadIdx.x & 31;
    int gw = blockIdx.x * 8 + warp;
    if (gw >= 2 * NTEST) return;
    int n = gw >> 1;
    bool is_base = (gw & 1);

    int p; const float* Xtr; float lls, los, lno;
    if (!is_base) {
        int e = g_route_e[n];
        if (nmask[e] == 0) {
            if (lane == 0) { g_mu_e[n] = 0.f; g_var_e[n] = 1.f; g_prior_e[n] = 1.f; }
            return;
        }
        p = e; Xtr = X_exp + (size_t)e * TN * DDIM;
        lls = lls_e[e]; los = los_e[e]; lno = lno_e[e];
    } else {
        int g = g_route_g[n];
        p = NEXP + g; Xtr = X_base + (size_t)g * TN * DDIM;
        lls = lls_b[g]; los = los_b[g]; lno = lno_b[g];
    }
    float ls2 = expf(2.f * lls);
    float osv = expf(los);
    float nv  = expf(lno) + JIT;
    float c0  = -0.5f / ls2;

    float xt[DDIM];
#pragma unroll
    for (int d = 0; d < DDIM; ++d) xt[d] = Xt[n * DDIM + d];

    // kstar, 8 rows per lane
    float ks[8];
#pragma unroll
    for (int t = 0; t < 8; ++t) {
        int r = 32 * t + lane;
        float d2 = 0.f;
#pragma unroll
        for (int d = 0; d < DDIM; ++d) {
            float tv = xt[d] - Xtr[r * DDIM + d];
            d2 += tv * tv;
        }
        ks[t] = osv * __expf(c0 * d2);
    }

    const float* Lp  = g_L    + (size_t)p * PACK;
    const float* inv = g_invd + p * TN;
    const float* wv  = g_w    + p * TN;
    float* z = sZ[warp];

    float qq = 0.f;
#pragma unroll 1
    for (int T = 0; T < 8; ++T) {
        int r  = 32 * T + lane;
        int cb = 32 * T;
        float invv = inv[r];
        // prefetch diag-block column values early (independent of solve)
        float dcol[32];
#pragma unroll
        for (int s = 0; s < 32; ++s)
            dcol[s] = Lp[cpidx(cb + s) + (lane - s)];

        // GEMV vs previous z: 4 independent accumulators
        float a0 = 0.f, a1 = 0.f, a2 = 0.f, a3 = 0.f;
        int idx = r;
#pragma unroll 2
        for (int c = 0; c < cb; c += 4) {
            float z0 = z[c], z1 = z[c+1], z2 = z[c+2], z3 = z[c+3];
            float l0 = Lp[idx]; idx += 255 - c;
            float l1 = Lp[idx]; idx += 254 - c;
            float l2 = Lp[idx]; idx += 253 - c;
            float l3 = Lp[idx]; idx += 252 - c;
            a0 += l0 * z0; a1 += l1 * z1; a2 += l2 * z2; a3 += l3 * z3;
        }
        float acc = ks[T] - ((a0 + a1) + (a2 + a3));

        float myz = 0.f;
#pragma unroll
        for (int s = 0; s < 32; ++s) {
            float zc = __shfl_sync(0xffffffffu, acc, s) * __shfl_sync(0xffffffffu, invv, s);
            if (lane == s) { myz = zc; qq += zc * zc; }
            if (lane > s) acc -= dcol[s] * zc;
        }
        z[r] = myz;
        __syncwarp();
    }

    // mu = v . w  (v in z[], w per problem)
    float mu = 0.f;
#pragma unroll
    for (int t = 0; t < 8; ++t) {
        int r = 32 * t + lane;
        mu += z[r] * wv[r];
    }
#pragma unroll
    for (int o = 16; o; o >>= 1) {
        mu += __shfl_xor_sync(0xffffffffu, mu, o);
        qq += __shfl_xor_sync(0xffffffffu, qq, o);
    }
    if (lane == 0) {
        float var = fmaxf(osv - qq, JIT) + nv;
        float prior = osv + nv;
        if (!is_base) { g_mu_e[n] = mu; g_var_e[n] = var; g_prior_e[n] = prior; }
        else          { g_mu_b[n] = mu; g_var_b[n] = var; g_prior_b[n] = prior; }
    }
}

// ---------------- kernel 4: rBCM combine ----------------
__global__ void k_combine(const int* __restrict__ nmask, float* __restrict__ out)
{
    int n = blockIdx.x * blockDim.x + threadIdx.x;
    if (n >= NTEST) return;
    int e = g_route_e[n];
    bool isnull = (nmask[e] == 0);
    float mue = g_mu_e[n], vare = g_var_e[n], pre = g_prior_e[n];
    float mub = g_mu_b[n], varb = g_var_b[n], prb = g_prior_b[n];
    float be = isnull ? 0.f : fmaxf(0.5f * (logf(pre) - logf(vare)), 0.f);
    float bb = fmaxf(0.5f * (logf(prb) - logf(varb)), 0.f);
    float prec = be / vare + bb / varb + (1.f - be - bb) / prb;
    prec = fmaxf(prec, 1e-6f);
    float mean = (be * mue / vare + bb * mub / varb) / prec;
    out[n] = mean;
    out[NTEST + n] = 1.f / prec;
}

// ---------------- launch ----------------
extern "C" void kernel_launch(void* const* d_in, const int* in_sizes, int n_in,
                              void* d_out, int out_size)
{
    const float* X_test   = (const float*)d_in[0];
    const float* X_exp    = (const float*)d_in[1];
    const float* Y_exp    = (const float*)d_in[2];
    const float* X_base   = (const float*)d_in[3];
    const float* Y_base   = (const float*)d_in[4];
    const float* lls_e    = (const float*)d_in[5];
    const float* los_e    = (const float*)d_in[6];
    const float* lno_e    = (const float*)d_in[7];
    const float* lls_b    = (const float*)d_in[8];
    const float* los_b    = (const float*)d_in[9];
    const float* lno_b    = (const float*)d_in[10];
    const float* smean    = (const float*)d_in[11];
    const float* sscale   = (const float*)d_in[12];
    const float* gm       = (const float*)d_in[13];
    const float* glv      = (const float*)d_in[14];
    const float* glw      = (const float*)d_in[15];
    const float* pm       = (const float*)d_in[16];
    const float* plv      = (const float*)d_in[17];
    const float* plw      = (const float*)d_in[18];
    const int*   nmask    = (const int*)d_in[19];
    float* out = (float*)d_out;

    static_assert(SMEM_FLOATS * 4 <= 232448, "smem");
    cudaFuncSetAttribute(k_factor, cudaFuncAttributeMaxDynamicSharedMemorySize,
                         SMEM_FLOATS * 4);

    k_zero<<<(NPROB + 255) / 256, 256>>>();
    k_route<<<(NTEST + 255) / 256, 256>>>(X_test, smean, sscale, gm, glv, glw,
                                          pm, plv, plw, nmask);
    k_factor<<<NPROB, 512, SMEM_FLOATS * 4>>>(X_exp, Y_exp, X_base, Y_base,
                                              lls_e, los_e, lno_e,
                                              lls_b, los_b, lno_b);
    k_predict<<<(2 * NTEST + 7) / 8, 256>>>(X_test, X_exp, X_base,
                                            lls_e, los_e, lno_e,
                                            lls_b, los_b, lno_b, nmask);
    k_combine<<<(NTEST + 255) / 256, 256>>>(nmask, out);
}